// round 2
// baseline (speedup 1.0000x reference)
#include <cuda_runtime.h>
#include <cuda_fp16.h>
#include <cstdint>

// Problem dims
#define V_TOT   32000
#define F_DIM   256
#define D_DIM   1024
#define R_TOT   8192      // B*N*T' = 4*64*32 rows

// Tiling
#define M_TILE  64
#define D_TILE  512
#define KV      32
#define N_CHUNK (V_TOT / KV)   // 1000

// SMEM pitches (halves), padded +8 for conflict-free ldmatrix
#define XPITCH  264
#define WPITCH  264
#define EPITCH  520
#define PPITCH  40

// Static device scratch (no cudaMalloc allowed)
__device__ __half g_W16[(size_t)V_TOT * F_DIM];   // W^T as (v, f), fp16
__device__ __half g_E16[(size_t)V_TOT * D_DIM];   // E as (v, d), fp16
__device__ __half g_X16[(size_t)R_TOT * F_DIM];   // permuted x as (r, f), fp16

// ---------------- PTX helpers ----------------
__device__ __forceinline__ unsigned saddr(const void* p) {
    return (unsigned)__cvta_generic_to_shared(p);
}
__device__ __forceinline__ void ldsm4(unsigned& r0, unsigned& r1, unsigned& r2, unsigned& r3, unsigned a) {
    asm volatile("ldmatrix.sync.aligned.m8n8.x4.shared.b16 {%0,%1,%2,%3},[%4];"
                 : "=r"(r0), "=r"(r1), "=r"(r2), "=r"(r3) : "r"(a));
}
__device__ __forceinline__ void ldsm2(unsigned& r0, unsigned& r1, unsigned a) {
    asm volatile("ldmatrix.sync.aligned.m8n8.x2.shared.b16 {%0,%1},[%2];"
                 : "=r"(r0), "=r"(r1) : "r"(a));
}
__device__ __forceinline__ void ldsm4t(unsigned& r0, unsigned& r1, unsigned& r2, unsigned& r3, unsigned a) {
    asm volatile("ldmatrix.sync.aligned.m8n8.x4.trans.shared.b16 {%0,%1,%2,%3},[%4];"
                 : "=r"(r0), "=r"(r1), "=r"(r2), "=r"(r3) : "r"(a));
}
__device__ __forceinline__ void mma16816(float* c, const unsigned* a, unsigned b0, unsigned b1) {
    asm volatile(
        "mma.sync.aligned.m16n8k16.row.col.f32.f16.f16.f32 "
        "{%0,%1,%2,%3},{%4,%5,%6,%7},{%8,%9},{%0,%1,%2,%3};"
        : "+f"(c[0]), "+f"(c[1]), "+f"(c[2]), "+f"(c[3])
        : "r"(a[0]), "r"(a[1]), "r"(a[2]), "r"(a[3]), "r"(b0), "r"(b1));
}
__device__ __forceinline__ void cp16(void* dst_sm, const void* src) {
    unsigned d = saddr(dst_sm);
    asm volatile("cp.async.cg.shared.global [%0],[%1],16;" :: "r"(d), "l"(src) : "memory");
}
__device__ __forceinline__ void cp_commit() {
    asm volatile("cp.async.commit_group;" ::: "memory");
}
template <int N>
__device__ __forceinline__ void cp_wait() {
    asm volatile("cp.async.wait_group %0;" :: "n"(N) : "memory");
}

// ---------------- preprocessing kernels ----------------
// W (f=256 rows, v=32000 cols, row-major) -> g_W16[v][f], tiled transpose
__global__ void cvt_w(const float* __restrict__ W) {
    __shared__ float t[32][33];
    int v0 = blockIdx.x * 32, f0 = blockIdx.y * 32;
    int tx = threadIdx.x, ty = threadIdx.y;  // (32,8)
#pragma unroll
    for (int k = 0; k < 32; k += 8)
        t[ty + k][tx] = W[(size_t)(f0 + ty + k) * V_TOT + v0 + tx];
    __syncthreads();
#pragma unroll
    for (int k = 0; k < 32; k += 8)
        g_W16[(size_t)(v0 + ty + k) * F_DIM + f0 + tx] = __float2half(t[tx][ty + k]);
}

// E (v,d) fp32 -> fp16 same layout
__global__ void cvt_e(const float4* __restrict__ E) {
    int i = blockIdx.x * blockDim.x + threadIdx.x;  // 8,192,000 float4s
    float4 v = E[i];
    __half2* dst = (__half2*)g_E16;
    dst[2 * (size_t)i]     = __floats2half2_rn(v.x, v.y);
    dst[2 * (size_t)i + 1] = __floats2half2_rn(v.z, v.w);
}

// x_prime (B,N,F,T) -> g_X16[r][f], r = b*2048 + t*64 + n
__global__ void cvt_x(const float* __restrict__ x) {
    __shared__ float sm[256][33];
    int bn = blockIdx.x;          // 0..255
    int b = bn >> 6, n = bn & 63;
    const float* src = x + ((size_t)b * 64 + n) * (F_DIM * 32);
    int tid = threadIdx.x;        // 256
#pragma unroll 4
    for (int i = tid; i < F_DIM * 32; i += 256) {
        int f = i >> 5, t = i & 31;
        sm[f][t] = src[i];
    }
    __syncthreads();
#pragma unroll 4
    for (int t = 0; t < 32; ++t) {
        int r = b * 2048 + t * 64 + n;
        g_X16[(size_t)r * F_DIM + tid] = __float2half(sm[tid][t]);
    }
}

// ---------------- fused main kernel ----------------
// grid: (D_DIM/D_TILE = 2, R_TOT/M_TILE = 128), 256 threads
#define SMEM_BYTES (M_TILE*XPITCH*2 + 2*KV*WPITCH*2 + 2*KV*EPITCH*2 + M_TILE*PPITCH*2 + 2*KV*4 + M_TILE*4)

__global__ void __launch_bounds__(256, 1)
fused_kernel(const float* __restrict__ bias, float* __restrict__ out) {
    extern __shared__ char smem_raw[];
    __half* Xs   = (__half*)smem_raw;
    __half* Wb   = Xs + M_TILE * XPITCH;
    __half* Eb   = Wb + 2 * KV * WPITCH;
    __half* Ps   = Eb + 2 * KV * EPITCH;
    float*  bsm  = (float*)(Ps + M_TILE * PPITCH);
    float*  rsum = bsm + 2 * KV;

    const int tid    = threadIdx.x;
    const int lane   = tid & 31;
    const int wid    = tid >> 5;
    const int warp_m = wid >> 2;   // 0..1  (32 rows each)
    const int warp_n = wid & 3;    // 0..3
    const int row_base = blockIdx.y * M_TILE;
    const int d_base   = blockIdx.x * D_TILE;

    // Load X tile (64 x 256 fp16) into smem
    {
        const __half* src = g_X16 + (size_t)row_base * F_DIM;
        for (int i = tid; i < M_TILE * (F_DIM / 8); i += 256) {
            int r = i >> 5, s = i & 31;
            *(uint4*)&Xs[r * XPITCH + s * 8] = *(const uint4*)&src[(size_t)r * F_DIM + s * 8];
        }
    }
    if (tid < M_TILE) rsum[tid] = 0.f;

    float hacc[2][16][4];
#pragma unroll
    for (int a = 0; a < 2; a++)
#pragma unroll
        for (int b = 0; b < 16; b++)
#pragma unroll
            for (int c = 0; c < 4; c++) hacc[a][b][c] = 0.f;
    float rs[4] = {0.f, 0.f, 0.f, 0.f};

    auto issue_chunk = [&](int c) {
        int st = c & 1;
        int v0 = c * KV;
        __half* Wd = Wb + st * KV * WPITCH;
        __half* Ed = Eb + st * KV * EPITCH;
#pragma unroll
        for (int i = 0; i < 4; ++i) {        // KV*32 = 1024 segs of 16B
            int idx = tid + i * 256;
            int r = idx >> 5, s = idx & 31;
            cp16(Wd + r * WPITCH + s * 8, g_W16 + (size_t)(v0 + r) * F_DIM + s * 8);
        }
#pragma unroll
        for (int i = 0; i < 8; ++i) {        // KV*64 = 2048 segs of 16B
            int idx = tid + i * 256;
            int r = idx >> 6, s = idx & 63;
            cp16(Ed + r * EPITCH + s * 8, g_E16 + (size_t)(v0 + r) * D_DIM + d_base + s * 8);
        }
        if (tid < 8) cp16(bsm + st * KV + tid * 4, bias + v0 + tid * 4);
        cp_commit();
    };

    issue_chunk(0);

    for (int c = 0; c < N_CHUNK; ++c) {
        if (c + 1 < N_CHUNK) { issue_chunk(c + 1); cp_wait<1>(); }
        else                 { cp_wait<0>(); }
        __syncthreads();

        const int st = c & 1;
        const __half* Wst = Wb + st * KV * WPITCH;
        const __half* Est = Eb + st * KV * EPITCH;
        const float*  bst = bsm + st * KV;

        // ---- GEMM1: S(64x32) = X(64x256) @ Wt^T ----
        float c1[2][4] = {{0.f,0.f,0.f,0.f},{0.f,0.f,0.f,0.f}};
#pragma unroll
        for (int ks = 0; ks < F_DIM / 16; ++ks) {
            unsigned a0[4], a1[4];
            {
                unsigned ad = saddr(Xs + (warp_m * 32 + (lane & 15)) * XPITCH + ks * 16 + ((lane >> 4) << 3));
                ldsm4(a0[0], a0[1], a0[2], a0[3], ad);
            }
            {
                unsigned ad = saddr(Xs + (warp_m * 32 + 16 + (lane & 15)) * XPITCH + ks * 16 + ((lane >> 4) << 3));
                ldsm4(a1[0], a1[1], a1[2], a1[3], ad);
            }
            unsigned b0, b1;
            {
                int l = lane & 15;
                unsigned bd = saddr(Wst + (warp_n * 8 + (l & 7)) * WPITCH + ks * 16 + ((l >> 3) << 3));
                ldsm2(b0, b1, bd);
            }
            mma16816(c1[0], a0, b0, b1);
            mma16816(c1[1], a1, b0, b1);
        }

        // ---- exp -> P (fp16), rowsum partials ----
        {
            int c0 = warp_n * 8 + (lane & 3) * 2;
            float bv0 = bst[c0], bv1 = bst[c0 + 1];
#pragma unroll
            for (int mt = 0; mt < 2; ++mt) {
                int r0 = warp_m * 32 + mt * 16 + (lane >> 2);
                float e0 = __expf(c1[mt][0] + bv0);
                float e1 = __expf(c1[mt][1] + bv1);
                __half2 h01 = __floats2half2_rn(e0, e1);
                *(__half2*)(Ps + r0 * PPITCH + c0) = h01;
                rs[mt * 2]     += __low2float(h01) + __high2float(h01);
                float e2 = __expf(c1[mt][2] + bv0);
                float e3 = __expf(c1[mt][3] + bv1);
                __half2 h23 = __floats2half2_rn(e2, e3);
                *(__half2*)(Ps + (r0 + 8) * PPITCH + c0) = h23;
                rs[mt * 2 + 1] += __low2float(h23) + __high2float(h23);
            }
        }
        __syncthreads();

        // ---- GEMM2: Hacc(64x512) += P(64x32) @ E(32x512) ----
#pragma unroll
        for (int ks = 0; ks < KV / 16; ++ks) {
            unsigned a0[4], a1[4];
            {
                unsigned ad = saddr(Ps + (warp_m * 32 + (lane & 15)) * PPITCH + ks * 16 + ((lane >> 4) << 3));
                ldsm4(a0[0], a0[1], a0[2], a0[3], ad);
            }
            {
                unsigned ad = saddr(Ps + (warp_m * 32 + 16 + (lane & 15)) * PPITCH + ks * 16 + ((lane >> 4) << 3));
                ldsm4(a1[0], a1[1], a1[2], a1[3], ad);
            }
#pragma unroll
            for (int np = 0; np < 8; ++np) {
                int d0 = warp_n * 128 + np * 16;
                unsigned b0, b1, b2, b3;
                unsigned bd = saddr(Est + (ks * 16 + (lane & 15)) * EPITCH + d0 + ((lane >> 4) << 3));
                ldsm4t(b0, b1, b2, b3, bd);
                mma16816(hacc[0][np * 2],     a0, b0, b1);
                mma16816(hacc[1][np * 2],     a1, b0, b1);
                mma16816(hacc[0][np * 2 + 1], a0, b2, b3);
                mma16816(hacc[1][np * 2 + 1], a1, b2, b3);
            }
        }
        __syncthreads();
    }

    // ---- rowsum reduce ----
#pragma unroll
    for (int j = 0; j < 4; ++j) {
        rs[j] += __shfl_xor_sync(0xffffffffu, rs[j], 1);
        rs[j] += __shfl_xor_sync(0xffffffffu, rs[j], 2);
    }
    if ((lane & 3) == 0) {
#pragma unroll
        for (int j = 0; j < 4; ++j) {
            int row = warp_m * 32 + (j >> 1) * 16 + (lane >> 2) + (j & 1) * 8;
            atomicAdd(&rsum[row], rs[j]);
        }
    }
    __syncthreads();

    float inv[2][2];
#pragma unroll
    for (int mt = 0; mt < 2; ++mt)
#pragma unroll
        for (int hi = 0; hi < 2; ++hi)
            inv[mt][hi] = 1.f / rsum[warp_m * 32 + mt * 16 + (lane >> 2) + hi * 8];

#pragma unroll
    for (int mt = 0; mt < 2; ++mt) {
        int r0 = row_base + warp_m * 32 + mt * 16 + (lane >> 2);
#pragma unroll
        for (int nt = 0; nt < 16; ++nt) {
            int col = d_base + warp_n * 128 + nt * 8 + (lane & 3) * 2;
            float2 v0 = make_float2(hacc[mt][nt][0] * inv[mt][0], hacc[mt][nt][1] * inv[mt][0]);
            *(float2*)&out[(size_t)r0 * D_DIM + col] = v0;
            float2 v1 = make_float2(hacc[mt][nt][2] * inv[mt][1], hacc[mt][nt][3] * inv[mt][1]);
            *(float2*)&out[(size_t)(r0 + 8) * D_DIM + col] = v1;
        }
    }
}

// ---------------- launch ----------------
extern "C" void kernel_launch(void* const* d_in, const int* in_sizes, int n_in,
                              void* d_out, int out_size) {
    const float* x   = (const float*)d_in[0];  // (4,64,256,32)
    const float* emb = (const float*)d_in[1];  // (32000,1024)
    const float* W   = (const float*)d_in[2];  // (256,32000)
    const float* b   = (const float*)d_in[3];  // (32000,)
    float* out = (float*)d_out;                // (4,2048,1024)

    cvt_w<<<dim3(V_TOT / 32, F_DIM / 32), dim3(32, 8)>>>(W);
    cvt_e<<<(V_TOT * (D_DIM / 4)) / 256, 256>>>((const float4*)emb);
    cvt_x<<<256, 256>>>(x);

    cudaFuncSetAttribute(fused_kernel, cudaFuncAttributeMaxDynamicSharedMemorySize, SMEM_BYTES);
    fused_kernel<<<dim3(D_DIM / D_TILE, R_TOT / M_TILE), 256, SMEM_BYTES>>>(b, out);
}

// round 3
// speedup vs baseline: 1.0005x; 1.0005x over previous
#include <cuda_runtime.h>
#include <cuda_fp16.h>
#include <cstdint>

// Problem dims
#define V_TOT   32000
#define F_DIM   256
#define D_DIM   1024
#define R_TOT   8192      // B*N*T' = 4*64*32 rows

// Tiling
#define M_TILE  64
#define D_TILE  512
#define KV      32
#define N_CHUNK (V_TOT / KV)   // 1000

// SMEM pitches (halves), padded +8 for conflict-free ldmatrix
#define XPITCH  264
#define WPITCH  264
#define EPITCH  520
#define PPITCH  40

// Static device scratch (no cudaMalloc allowed)
__device__ __half g_W16[(size_t)V_TOT * F_DIM];   // W^T as (v, f), fp16
__device__ __half g_E16[(size_t)V_TOT * D_DIM];   // E as (v, d), fp16
__device__ __half g_X16[(size_t)R_TOT * F_DIM];   // permuted x as (r, f), fp16

// ---------------- PTX helpers ----------------
__device__ __forceinline__ unsigned saddr(const void* p) {
    return (unsigned)__cvta_generic_to_shared(p);
}
__device__ __forceinline__ void ldsm4(unsigned& r0, unsigned& r1, unsigned& r2, unsigned& r3, unsigned a) {
    asm volatile("ldmatrix.sync.aligned.m8n8.x4.shared.b16 {%0,%1,%2,%3},[%4];"
                 : "=r"(r0), "=r"(r1), "=r"(r2), "=r"(r3) : "r"(a));
}
__device__ __forceinline__ void ldsm2(unsigned& r0, unsigned& r1, unsigned a) {
    asm volatile("ldmatrix.sync.aligned.m8n8.x2.shared.b16 {%0,%1},[%2];"
                 : "=r"(r0), "=r"(r1) : "r"(a));
}
__device__ __forceinline__ void ldsm4t(unsigned& r0, unsigned& r1, unsigned& r2, unsigned& r3, unsigned a) {
    asm volatile("ldmatrix.sync.aligned.m8n8.x4.trans.shared.b16 {%0,%1,%2,%3},[%4];"
                 : "=r"(r0), "=r"(r1), "=r"(r2), "=r"(r3) : "r"(a));
}
__device__ __forceinline__ void mma16816(float* c, const unsigned* a, unsigned b0, unsigned b1) {
    asm volatile(
        "mma.sync.aligned.m16n8k16.row.col.f32.f16.f16.f32 "
        "{%0,%1,%2,%3},{%4,%5,%6,%7},{%8,%9},{%0,%1,%2,%3};"
        : "+f"(c[0]), "+f"(c[1]), "+f"(c[2]), "+f"(c[3])
        : "r"(a[0]), "r"(a[1]), "r"(a[2]), "r"(a[3]), "r"(b0), "r"(b1));
}
__device__ __forceinline__ void cp16(void* dst_sm, const void* src) {
    unsigned d = saddr(dst_sm);
    asm volatile("cp.async.cg.shared.global [%0],[%1],16;" :: "r"(d), "l"(src) : "memory");
}
__device__ __forceinline__ void cp_commit() {
    asm volatile("cp.async.commit_group;" ::: "memory");
}
template <int N>
__device__ __forceinline__ void cp_wait() {
    asm volatile("cp.async.wait_group %0;" :: "n"(N) : "memory");
}

// ---------------- preprocessing kernels ----------------
// W (f=256 rows, v=32000 cols, row-major) -> g_W16[v][f], tiled transpose
__global__ void cvt_w(const float* __restrict__ W) {
    __shared__ float t[32][33];
    int v0 = blockIdx.x * 32, f0 = blockIdx.y * 32;
    int tx = threadIdx.x, ty = threadIdx.y;  // (32,8)
#pragma unroll
    for (int k = 0; k < 32; k += 8)
        t[ty + k][tx] = W[(size_t)(f0 + ty + k) * V_TOT + v0 + tx];
    __syncthreads();
#pragma unroll
    for (int k = 0; k < 32; k += 8)
        g_W16[(size_t)(v0 + ty + k) * F_DIM + f0 + tx] = __float2half(t[tx][ty + k]);
}

// E (v,d) fp32 -> fp16 same layout
__global__ void cvt_e(const float4* __restrict__ E) {
    int i = blockIdx.x * blockDim.x + threadIdx.x;  // 8,192,000 float4s
    float4 v = E[i];
    __half2* dst = (__half2*)g_E16;
    dst[2 * (size_t)i]     = __floats2half2_rn(v.x, v.y);
    dst[2 * (size_t)i + 1] = __floats2half2_rn(v.z, v.w);
}

// x_prime (B,N,F,T) -> g_X16[r][f], r = b*2048 + t*64 + n
__global__ void cvt_x(const float* __restrict__ x) {
    __shared__ float sm[256][33];
    int bn = blockIdx.x;          // 0..255
    int b = bn >> 6, n = bn & 63;
    const float* src = x + ((size_t)b * 64 + n) * (F_DIM * 32);
    int tid = threadIdx.x;        // 256
#pragma unroll 4
    for (int i = tid; i < F_DIM * 32; i += 256) {
        int f = i >> 5, t = i & 31;
        sm[f][t] = src[i];
    }
    __syncthreads();
#pragma unroll 4
    for (int t = 0; t < 32; ++t) {
        int r = b * 2048 + t * 64 + n;
        g_X16[(size_t)r * F_DIM + tid] = __float2half(sm[tid][t]);
    }
}

// ---------------- fused main kernel ----------------
// grid: (D_DIM/D_TILE = 2, R_TOT/M_TILE = 128), 256 threads
#define SMEM_BYTES (M_TILE*XPITCH*2 + 2*KV*WPITCH*2 + 2*KV*EPITCH*2 + M_TILE*PPITCH*2 + 2*KV*4 + M_TILE*4)

__global__ void __launch_bounds__(256, 1)
fused_kernel(const float* __restrict__ bias, float* __restrict__ out) {
    extern __shared__ char smem_raw[];
    __half* Xs   = (__half*)smem_raw;
    __half* Wb   = Xs + M_TILE * XPITCH;
    __half* Eb   = Wb + 2 * KV * WPITCH;
    __half* Ps   = Eb + 2 * KV * EPITCH;
    float*  bsm  = (float*)(Ps + M_TILE * PPITCH);
    float*  rsum = bsm + 2 * KV;

    const int tid    = threadIdx.x;
    const int lane   = tid & 31;
    const int wid    = tid >> 5;
    const int warp_m = wid >> 2;   // 0..1  (32 rows each)
    const int warp_n = wid & 3;    // 0..3
    const int row_base = blockIdx.y * M_TILE;
    const int d_base   = blockIdx.x * D_TILE;

    // Load X tile (64 x 256 fp16) into smem
    {
        const __half* src = g_X16 + (size_t)row_base * F_DIM;
        for (int i = tid; i < M_TILE * (F_DIM / 8); i += 256) {
            int r = i >> 5, s = i & 31;
            *(uint4*)&Xs[r * XPITCH + s * 8] = *(const uint4*)&src[(size_t)r * F_DIM + s * 8];
        }
    }
    if (tid < M_TILE) rsum[tid] = 0.f;

    float hacc[2][16][4];
#pragma unroll
    for (int a = 0; a < 2; a++)
#pragma unroll
        for (int b = 0; b < 16; b++)
#pragma unroll
            for (int c = 0; c < 4; c++) hacc[a][b][c] = 0.f;
    float rs[4] = {0.f, 0.f, 0.f, 0.f};

    auto issue_chunk = [&](int c) {
        int st = c & 1;
        int v0 = c * KV;
        __half* Wd = Wb + st * KV * WPITCH;
        __half* Ed = Eb + st * KV * EPITCH;
#pragma unroll
        for (int i = 0; i < 4; ++i) {        // KV*32 = 1024 segs of 16B
            int idx = tid + i * 256;
            int r = idx >> 5, s = idx & 31;
            cp16(Wd + r * WPITCH + s * 8, g_W16 + (size_t)(v0 + r) * F_DIM + s * 8);
        }
#pragma unroll
        for (int i = 0; i < 8; ++i) {        // KV*64 = 2048 segs of 16B
            int idx = tid + i * 256;
            int r = idx >> 6, s = idx & 63;
            cp16(Ed + r * EPITCH + s * 8, g_E16 + (size_t)(v0 + r) * D_DIM + d_base + s * 8);
        }
        if (tid < 8) cp16(bsm + st * KV + tid * 4, bias + v0 + tid * 4);
        cp_commit();
    };

    issue_chunk(0);

    for (int c = 0; c < N_CHUNK; ++c) {
        if (c + 1 < N_CHUNK) { issue_chunk(c + 1); cp_wait<1>(); }
        else                 { cp_wait<0>(); }
        __syncthreads();

        const int st = c & 1;
        const __half* Wst = Wb + st * KV * WPITCH;
        const __half* Est = Eb + st * KV * EPITCH;
        const float*  bst = bsm + st * KV;

        // ---- GEMM1: S(64x32) = X(64x256) @ Wt^T ----
        float c1[2][4] = {{0.f,0.f,0.f,0.f},{0.f,0.f,0.f,0.f}};
#pragma unroll
        for (int ks = 0; ks < F_DIM / 16; ++ks) {
            unsigned a0[4], a1[4];
            {
                unsigned ad = saddr(Xs + (warp_m * 32 + (lane & 15)) * XPITCH + ks * 16 + ((lane >> 4) << 3));
                ldsm4(a0[0], a0[1], a0[2], a0[3], ad);
            }
            {
                unsigned ad = saddr(Xs + (warp_m * 32 + 16 + (lane & 15)) * XPITCH + ks * 16 + ((lane >> 4) << 3));
                ldsm4(a1[0], a1[1], a1[2], a1[3], ad);
            }
            unsigned b0, b1;
            {
                int l = lane & 15;
                unsigned bd = saddr(Wst + (warp_n * 8 + (l & 7)) * WPITCH + ks * 16 + ((l >> 3) << 3));
                ldsm2(b0, b1, bd);
            }
            mma16816(c1[0], a0, b0, b1);
            mma16816(c1[1], a1, b0, b1);
        }

        // ---- exp -> P (fp16), rowsum partials ----
        {
            int c0 = warp_n * 8 + (lane & 3) * 2;
            float bv0 = bst[c0], bv1 = bst[c0 + 1];
#pragma unroll
            for (int mt = 0; mt < 2; ++mt) {
                int r0 = warp_m * 32 + mt * 16 + (lane >> 2);
                float e0 = __expf(c1[mt][0] + bv0);
                float e1 = __expf(c1[mt][1] + bv1);
                __half2 h01 = __floats2half2_rn(e0, e1);
                *(__half2*)(Ps + r0 * PPITCH + c0) = h01;
                rs[mt * 2]     += __low2float(h01) + __high2float(h01);
                float e2 = __expf(c1[mt][2] + bv0);
                float e3 = __expf(c1[mt][3] + bv1);
                __half2 h23 = __floats2half2_rn(e2, e3);
                *(__half2*)(Ps + (r0 + 8) * PPITCH + c0) = h23;
                rs[mt * 2 + 1] += __low2float(h23) + __high2float(h23);
            }
        }
        __syncthreads();

        // ---- GEMM2: Hacc(64x512) += P(64x32) @ E(32x512) ----
#pragma unroll
        for (int ks = 0; ks < KV / 16; ++ks) {
            unsigned a0[4], a1[4];
            {
                unsigned ad = saddr(Ps + (warp_m * 32 + (lane & 15)) * PPITCH + ks * 16 + ((lane >> 4) << 3));
                ldsm4(a0[0], a0[1], a0[2], a0[3], ad);
            }
            {
                unsigned ad = saddr(Ps + (warp_m * 32 + 16 + (lane & 15)) * PPITCH + ks * 16 + ((lane >> 4) << 3));
                ldsm4(a1[0], a1[1], a1[2], a1[3], ad);
            }
#pragma unroll
            for (int np = 0; np < 8; ++np) {
                int d0 = warp_n * 128 + np * 16;
                unsigned b0, b1, b2, b3;
                unsigned bd = saddr(Est + (ks * 16 + (lane & 15)) * EPITCH + d0 + ((lane >> 4) << 3));
                ldsm4t(b0, b1, b2, b3, bd);
                mma16816(hacc[0][np * 2],     a0, b0, b1);
                mma16816(hacc[1][np * 2],     a1, b0, b1);
                mma16816(hacc[0][np * 2 + 1], a0, b2, b3);
                mma16816(hacc[1][np * 2 + 1], a1, b2, b3);
            }
        }
        __syncthreads();
    }

    // ---- rowsum reduce ----
#pragma unroll
    for (int j = 0; j < 4; ++j) {
        rs[j] += __shfl_xor_sync(0xffffffffu, rs[j], 1);
        rs[j] += __shfl_xor_sync(0xffffffffu, rs[j], 2);
    }
    if ((lane & 3) == 0) {
#pragma unroll
        for (int j = 0; j < 4; ++j) {
            int row = warp_m * 32 + (j >> 1) * 16 + (lane >> 2) + (j & 1) * 8;
            atomicAdd(&rsum[row], rs[j]);
        }
    }
    __syncthreads();

    float inv[2][2];
#pragma unroll
    for (int mt = 0; mt < 2; ++mt)
#pragma unroll
        for (int hi = 0; hi < 2; ++hi)
            inv[mt][hi] = 1.f / rsum[warp_m * 32 + mt * 16 + (lane >> 2) + hi * 8];

#pragma unroll
    for (int mt = 0; mt < 2; ++mt) {
        int r0 = row_base + warp_m * 32 + mt * 16 + (lane >> 2);
#pragma unroll
        for (int nt = 0; nt < 16; ++nt) {
            int col = d_base + warp_n * 128 + nt * 8 + (lane & 3) * 2;
            float2 v0 = make_float2(hacc[mt][nt][0] * inv[mt][0], hacc[mt][nt][1] * inv[mt][0]);
            *(float2*)&out[(size_t)r0 * D_DIM + col] = v0;
            float2 v1 = make_float2(hacc[mt][nt][2] * inv[mt][1], hacc[mt][nt][3] * inv[mt][1]);
            *(float2*)&out[(size_t)(r0 + 8) * D_DIM + col] = v1;
        }
    }
}

// ---------------- launch ----------------
extern "C" void kernel_launch(void* const* d_in, const int* in_sizes, int n_in,
                              void* d_out, int out_size) {
    const float* x   = (const float*)d_in[0];  // (4,64,256,32)
    const float* emb = (const float*)d_in[1];  // (32000,1024)
    const float* W   = (const float*)d_in[2];  // (256,32000)
    const float* b   = (const float*)d_in[3];  // (32000,)
    float* out = (float*)d_out;                // (4,2048,1024)

    cvt_w<<<dim3(V_TOT / 32, F_DIM / 32), dim3(32, 8)>>>(W);
    cvt_e<<<(V_TOT * (D_DIM / 4)) / 256, 256>>>((const float4*)emb);
    cvt_x<<<256, 256>>>(x);

    cudaFuncSetAttribute(fused_kernel, cudaFuncAttributeMaxDynamicSharedMemorySize, SMEM_BYTES);
    fused_kernel<<<dim3(D_DIM / D_TILE, R_TOT / M_TILE), 256, SMEM_BYTES>>>(b, out);
}

// round 6
// speedup vs baseline: 1.6909x; 1.6901x over previous
#include <cuda_runtime.h>
#include <cuda_fp16.h>
#include <cstdint>

#define V_TOT 32000
#define F_DIM 256
#define D_DIM 1024
#define R_TOT 8192

// pass A tiling (S = X @ W^T, then exp -> P)
#define AM 128
#define AV 128
// pass B tiling (H = P @ E)
#define BM 128
#define BD 256
#define BKV 64
#define BSTAGE 4
#define BNCH (V_TOT / BKV)   // 500

// smem pitches in halves (+8 halves pad)
#define XP 264
#define WP 264
#define PSP 136
#define PP 72
#define EP 264

// passA smem layout (halves)
#define A_X_OFF 0
#define A_W_OFF (AM * XP)
#define A_P_OFF (A_W_OFF + AV * WP)
#define A_SMEM_BYTES ((A_P_OFF + AM * PSP) * 2)          // 169,984 B

// passB smem layout (halves)
#define B_STAGE_H (BM * PP + BKV * EP)                   // 26112 halves
#define B_P_OFF 0
#define B_E_OFF (BM * PP)
#define B_SMEM_BYTES (BSTAGE * B_STAGE_H * 2)            // 208,896 B

// ---------------- static device scratch ----------------
__device__ __half g_W16[(size_t)V_TOT * F_DIM];   // (v, f) fp16
__device__ __half g_E16[(size_t)V_TOT * D_DIM];   // (v, d) fp16
__device__ __half g_X16[(size_t)R_TOT * F_DIM];   // (r, f) fp16 (permuted)
__device__ __half g_P[(size_t)R_TOT * V_TOT];     // (r, v) fp16 unnormalized probs
__device__ float  g_rsum[R_TOT];                  // per-row sum of exp

// ---------------- PTX helpers ----------------
__device__ __forceinline__ unsigned saddr(const void* p) {
    return (unsigned)__cvta_generic_to_shared(p);
}
__device__ __forceinline__ void ldsm4(unsigned& r0, unsigned& r1, unsigned& r2, unsigned& r3, unsigned a) {
    asm volatile("ldmatrix.sync.aligned.m8n8.x4.shared.b16 {%0,%1,%2,%3},[%4];"
                 : "=r"(r0), "=r"(r1), "=r"(r2), "=r"(r3) : "r"(a));
}
__device__ __forceinline__ void ldsm4t(unsigned& r0, unsigned& r1, unsigned& r2, unsigned& r3, unsigned a) {
    asm volatile("ldmatrix.sync.aligned.m8n8.x4.trans.shared.b16 {%0,%1,%2,%3},[%4];"
                 : "=r"(r0), "=r"(r1), "=r"(r2), "=r"(r3) : "r"(a));
}
__device__ __forceinline__ void mma16816(float* c, const unsigned* a, unsigned b0, unsigned b1) {
    asm volatile(
        "mma.sync.aligned.m16n8k16.row.col.f32.f16.f16.f32 "
        "{%0,%1,%2,%3},{%4,%5,%6,%7},{%8,%9},{%0,%1,%2,%3};"
        : "+f"(c[0]), "+f"(c[1]), "+f"(c[2]), "+f"(c[3])
        : "r"(a[0]), "r"(a[1]), "r"(a[2]), "r"(a[3]), "r"(b0), "r"(b1));
}
__device__ __forceinline__ void cp16(unsigned dst, const void* src) {
    asm volatile("cp.async.cg.shared.global [%0],[%1],16;" :: "r"(dst), "l"(src) : "memory");
}
#define CP_COMMIT() asm volatile("cp.async.commit_group;" ::: "memory")
template <int N> __device__ __forceinline__ void cp_wait() {
    asm volatile("cp.async.wait_group %0;" :: "n"(N) : "memory");
}

// ---------------- prep kernels (proven in round 1) ----------------
__global__ void cvt_w(const float* __restrict__ W) {      // (f,v) f32 -> (v,f) f16
    __shared__ float t[32][33];
    int v0 = blockIdx.x * 32, f0 = blockIdx.y * 32;
    int tx = threadIdx.x, ty = threadIdx.y;  // (32,8)
#pragma unroll
    for (int k = 0; k < 32; k += 8)
        t[ty + k][tx] = W[(size_t)(f0 + ty + k) * V_TOT + v0 + tx];
    __syncthreads();
#pragma unroll
    for (int k = 0; k < 32; k += 8)
        g_W16[(size_t)(v0 + ty + k) * F_DIM + f0 + tx] = __float2half(t[tx][ty + k]);
}

__global__ void cvt_e(const float4* __restrict__ E) {     // (v,d) f32 -> (v,d) f16
    int i = blockIdx.x * blockDim.x + threadIdx.x;
    float4 v = E[i];
    __half2* dst = (__half2*)g_E16;
    dst[2 * (size_t)i]     = __floats2half2_rn(v.x, v.y);
    dst[2 * (size_t)i + 1] = __floats2half2_rn(v.z, v.w);
}

__global__ void cvt_x(const float* __restrict__ x) {      // (B,N,F,T) -> (r,f), r=b*2048+t*64+n
    __shared__ float sm[256][33];
    int bn = blockIdx.x;
    int b = bn >> 6, n = bn & 63;
    const float* src = x + ((size_t)b * 64 + n) * (F_DIM * 32);
    int tid = threadIdx.x;
#pragma unroll 4
    for (int i = tid; i < F_DIM * 32; i += 256) sm[i >> 5][i & 31] = src[i];
    __syncthreads();
#pragma unroll 4
    for (int t = 0; t < 32; ++t) {
        int r = b * 2048 + t * 64 + n;
        g_X16[(size_t)r * F_DIM + tid] = __float2half(sm[tid][t]);
    }
}

__global__ void zero_rsum() {
    g_rsum[blockIdx.x * 1024 + threadIdx.x] = 0.f;
}

// ---------------- pass A: P = exp(X @ W^T + b), rowsum atomics ----------------
// grid (V_TOT/AV = 250, R_TOT/AM = 64), 256 threads
__global__ void __launch_bounds__(256, 1)
passA(const float* __restrict__ bias) {
    extern __shared__ __align__(16) __half smem[];
    const unsigned sb = saddr(smem);
    const int tid  = threadIdx.x;
    const int lane = tid & 31;
    const int wid  = tid >> 5;
    const int warp_m = wid >> 1;    // 0..3 (32 rows)
    const int warp_n = wid & 1;     // 0..1 (64 cols)
    const int row_base = blockIdx.y * AM;
    const int v_base   = blockIdx.x * AV;

    // load X tile (128 x 256) and W tile (128v x 256)
    {
        const __half* Xsrc = g_X16 + (size_t)row_base * F_DIM;
        const __half* Wsrc = g_W16 + (size_t)v_base * F_DIM;
#pragma unroll
        for (int i = 0; i < 16; ++i) {
            int idx = tid + i * 256;            // 4096 segs of 16B
            int r = idx >> 5, s = idx & 31;
            cp16(sb + (A_X_OFF + r * XP + s * 8) * 2, Xsrc + (size_t)r * F_DIM + s * 8);
        }
#pragma unroll
        for (int i = 0; i < 16; ++i) {
            int idx = tid + i * 256;
            int r = idx >> 5, s = idx & 31;
            cp16(sb + (A_W_OFF + r * WP + s * 8) * 2, Wsrc + (size_t)r * F_DIM + s * 8);
        }
    }
    CP_COMMIT();
    cp_wait<0>();
    __syncthreads();

    float acc[2][8][4];
#pragma unroll
    for (int a = 0; a < 2; a++)
#pragma unroll
        for (int b = 0; b < 8; b++)
#pragma unroll
            for (int c = 0; c < 4; c++) acc[a][b][c] = 0.f;

    const int m_base = warp_m * 32;
#pragma unroll
    for (int ks = 0; ks < 16; ++ks) {
        unsigned a0[4], a1[4];
        ldsm4(a0[0], a0[1], a0[2], a0[3],
              sb + (A_X_OFF + (m_base + (lane & 15)) * XP + ks * 16 + ((lane >> 4) << 3)) * 2);
        ldsm4(a1[0], a1[1], a1[2], a1[3],
              sb + (A_X_OFF + (m_base + 16 + (lane & 15)) * XP + ks * 16 + ((lane >> 4) << 3)) * 2);
#pragma unroll
        for (int nb = 0; nb < 4; ++nb) {
            unsigned b0, b1, b2, b3;
            int wrow = warp_n * 64 + nb * 16 + ((lane >> 4) << 3) + (lane & 7);
            int koff = ks * 16 + (((lane >> 3) & 1) << 3);
            ldsm4(b0, b1, b2, b3, sb + (A_W_OFF + wrow * WP + koff) * 2);
            mma16816(acc[0][nb * 2],     a0, b0, b1);
            mma16816(acc[0][nb * 2 + 1], a0, b2, b3);
            mma16816(acc[1][nb * 2],     a1, b0, b1);
            mma16816(acc[1][nb * 2 + 1], a1, b2, b3);
        }
    }

    // exp -> fp16 stage + rowsum partials (sums from f16-rounded values)
    float rs[4] = {0.f, 0.f, 0.f, 0.f};
#pragma unroll
    for (int mt = 0; mt < 2; ++mt) {
        int r0 = m_base + mt * 16 + (lane >> 2);
#pragma unroll
        for (int nt = 0; nt < 8; ++nt) {
            int c0 = warp_n * 64 + nt * 8 + (lane & 3) * 2;
            float bv0 = __ldg(bias + v_base + c0);
            float bv1 = __ldg(bias + v_base + c0 + 1);
            float e0 = __expf(acc[mt][nt][0] + bv0);
            float e1 = __expf(acc[mt][nt][1] + bv1);
            __half2 h01 = __floats2half2_rn(e0, e1);
            *(__half2*)(smem + A_P_OFF + r0 * PSP + c0) = h01;
            rs[mt * 2] += __low2float(h01) + __high2float(h01);
            float e2 = __expf(acc[mt][nt][2] + bv0);
            float e3 = __expf(acc[mt][nt][3] + bv1);
            __half2 h23 = __floats2half2_rn(e2, e3);
            *(__half2*)(smem + A_P_OFF + (r0 + 8) * PSP + c0) = h23;
            rs[mt * 2 + 1] += __low2float(h23) + __high2float(h23);
        }
    }
#pragma unroll
    for (int j = 0; j < 4; ++j) {
        rs[j] += __shfl_xor_sync(0xffffffffu, rs[j], 1);
        rs[j] += __shfl_xor_sync(0xffffffffu, rs[j], 2);
    }
    if ((lane & 3) == 0) {
#pragma unroll
        for (int j = 0; j < 4; ++j) {
            int row = m_base + (j >> 1) * 16 + (lane >> 2) + (j & 1) * 8;
            atomicAdd(&g_rsum[row_base + row], rs[j]);
        }
    }
    __syncthreads();

    // coalesced copy stage -> g_P
#pragma unroll
    for (int i = 0; i < 8; ++i) {
        int idx = tid + i * 256;                // 2048 segs of 16B
        int r = idx >> 4, s = idx & 15;
        *(uint4*)(g_P + (size_t)(row_base + r) * V_TOT + v_base + s * 8) =
            *(const uint4*)(smem + A_P_OFF + r * PSP + s * 8);
    }
}

// ---------------- pass B: H = (P @ E) / rowsum ----------------
// grid (D_DIM/BD = 4, R_TOT/BM = 64), 512 threads (16 warps)
__global__ void __launch_bounds__(512, 1)
passB(float* __restrict__ out) {
    extern __shared__ __align__(16) __half smem[];
    const unsigned sb = saddr(smem);
    const int tid  = threadIdx.x;
    const int lane = tid & 31;
    const int wid  = tid >> 5;
    const int warp_m = wid >> 2;    // 0..3 (32 rows)
    const int warp_n = wid & 3;     // 0..3 (64 cols)
    const int row_base = blockIdx.y * BM;
    const int d_base   = blockIdx.x * BD;

    float hacc[2][8][4];
#pragma unroll
    for (int a = 0; a < 2; a++)
#pragma unroll
        for (int b = 0; b < 8; b++)
#pragma unroll
            for (int c = 0; c < 4; c++) hacc[a][b][c] = 0.f;

    auto issue_chunk = [&](int c) {
        const int st = c & (BSTAGE - 1);
        const unsigned ps = sb + (st * B_STAGE_H + B_P_OFF) * 2;
        const unsigned es = sb + (st * B_STAGE_H + B_E_OFF) * 2;
        const int v0 = c * BKV;
        // P: 128 rows x 8 segs (16B) = 1024
#pragma unroll
        for (int i = 0; i < 2; ++i) {
            int idx = tid + i * 512;
            int r = idx >> 3, s = idx & 7;
            cp16(ps + (r * PP + s * 8) * 2, g_P + (size_t)(row_base + r) * V_TOT + v0 + s * 8);
        }
        // E: 64 rows x 32 segs = 2048
#pragma unroll
        for (int i = 0; i < 4; ++i) {
            int idx = tid + i * 512;
            int r = idx >> 5, s = idx & 31;
            cp16(es + (r * EP + s * 8) * 2, g_E16 + (size_t)(v0 + r) * D_DIM + d_base + s * 8);
        }
        CP_COMMIT();
    };

    issue_chunk(0);
    issue_chunk(1);
    issue_chunk(2);

    const int m_base = warp_m * 32;
    for (int c = 0; c < BNCH; ++c) {
        cp_wait<2>();
        __syncthreads();

        const int st = c & (BSTAGE - 1);
        const unsigned ps = sb + (st * B_STAGE_H + B_P_OFF) * 2;
        const unsigned es = sb + (st * B_STAGE_H + B_E_OFF) * 2;

#pragma unroll
        for (int ks = 0; ks < 4; ++ks) {
            unsigned a0[4], a1[4];
            ldsm4(a0[0], a0[1], a0[2], a0[3],
                  ps + ((m_base + (lane & 15)) * PP + ks * 16 + ((lane >> 4) << 3)) * 2);
            ldsm4(a1[0], a1[1], a1[2], a1[3],
                  ps + ((m_base + 16 + (lane & 15)) * PP + ks * 16 + ((lane >> 4) << 3)) * 2);
#pragma unroll
            for (int np = 0; np < 4; ++np) {
                unsigned b0, b1, b2, b3;
                ldsm4t(b0, b1, b2, b3,
                       es + ((ks * 16 + (lane & 15)) * EP + warp_n * 64 + np * 16 + ((lane >> 4) << 3)) * 2);
                mma16816(hacc[0][np * 2],     a0, b0, b1);
                mma16816(hacc[0][np * 2 + 1], a0, b2, b3);
                mma16816(hacc[1][np * 2],     a1, b0, b1);
                mma16816(hacc[1][np * 2 + 1], a1, b2, b3);
            }
        }
        __syncthreads();

        if (c + 3 < BNCH) issue_chunk(c + 3);
        else CP_COMMIT();    // keep wait_group accounting uniform
    }

    // epilogue: scale by 1/rowsum, store f32
    float inv[2][2];
#pragma unroll
    for (int mt = 0; mt < 2; ++mt) {
#pragma unroll
        for (int h = 0; h < 2; ++h)
            inv[mt][h] = 1.f / __ldg(&g_rsum[row_base + m_base + mt * 16 + (lane >> 2) + h * 8]);
    }
#pragma unroll
    for (int mt = 0; mt < 2; ++mt) {
        int r0 = row_base + m_base + mt * 16 + (lane >> 2);
#pragma unroll
        for (int nt = 0; nt < 8; ++nt) {
            int col = d_base + warp_n * 64 + nt * 8 + (lane & 3) * 2;
            float2 v0 = make_float2(hacc[mt][nt][0] * inv[mt][0], hacc[mt][nt][1] * inv[mt][0]);
            *(float2*)&out[(size_t)r0 * D_DIM + col] = v0;
            float2 v1 = make_float2(hacc[mt][nt][2] * inv[mt][1], hacc[mt][nt][3] * inv[mt][1]);
            *(float2*)&out[(size_t)(r0 + 8) * D_DIM + col] = v1;
        }
    }
}

// ---------------- launch ----------------
extern "C" void kernel_launch(void* const* d_in, const int* in_sizes, int n_in,
                              void* d_out, int out_size) {
    const float* x   = (const float*)d_in[0];  // (4,64,256,32)
    const float* emb = (const float*)d_in[1];  // (32000,1024)
    const float* W   = (const float*)d_in[2];  // (256,32000)
    const float* b   = (const float*)d_in[3];  // (32000,)
    float* out = (float*)d_out;                // (4,2048,1024)

    cvt_w<<<dim3(V_TOT / 32, F_DIM / 32), dim3(32, 8)>>>(W);
    cvt_e<<<(V_TOT * (D_DIM / 4)) / 256, 256>>>((const float4*)emb);
    cvt_x<<<256, 256>>>(x);
    zero_rsum<<<R_TOT / 1024, 1024>>>();

    cudaFuncSetAttribute(passA, cudaFuncAttributeMaxDynamicSharedMemorySize, A_SMEM_BYTES);
    passA<<<dim3(V_TOT / AV, R_TOT / AM), 256, A_SMEM_BYTES>>>(b);

    cudaFuncSetAttribute(passB, cudaFuncAttributeMaxDynamicSharedMemorySize, B_SMEM_BYTES);
    passB<<<dim3(D_DIM / BD, R_TOT / BM), 512, B_SMEM_BYTES>>>(out);
}

// round 7
// speedup vs baseline: 1.8750x; 1.1088x over previous
#include <cuda_runtime.h>
#include <cuda_fp16.h>
#include <cstdint>

#define V_TOT 32000
#define F_DIM 256
#define D_DIM 1024
#define R_TOT 8192

// pass A tiling (S = X @ W^T, then exp -> P), k streamed in 4 slabs of 64
#define AM 128
#define AV 128
#define ASLAB 64
#define ANSLAB (F_DIM / ASLAB)   // 4
// pass B tiling (H = P @ E)
#define BM 128
#define BD 256
#define BKV 64
#define BSTAGE 4
#define BNCH (V_TOT / BKV)   // 500

// ---- passA smem (halves) ----
// stage: X slab [128][72] + W slab [128][72] ; 2 stages ; then P stage [128][136]
#define AXP 72
#define A_STAGE_H (2 * AM * AXP)                  // 18432 halves per stage
#define A_P_OFF   (2 * A_STAGE_H)                 // 36864
#define APSP 136
#define A_SMEM_BYTES ((A_P_OFF + AM * APSP) * 2)  // 108,544 B -> 2 CTAs/SM

// ---- passB smem (halves) ----
#define PP 72
#define EP 264
#define B_STAGE_H (BM * PP + BKV * EP)            // 26112 halves
#define B_P_OFF 0
#define B_E_OFF (BM * PP)
#define B_SMEM_BYTES (BSTAGE * B_STAGE_H * 2)     // 208,896 B

// ---------------- static device scratch ----------------
__device__ __half g_W16[(size_t)V_TOT * F_DIM];   // (v, f) fp16
__device__ __half g_E16[(size_t)V_TOT * D_DIM];   // (v, d) fp16
__device__ __half g_X16[(size_t)R_TOT * F_DIM];   // (r, f) fp16 (permuted)
__device__ __half g_P[(size_t)R_TOT * V_TOT];     // (r, v) fp16 unnormalized probs
__device__ float  g_rsum[R_TOT];                  // per-row sum of exp

// ---------------- PTX helpers ----------------
__device__ __forceinline__ unsigned saddr(const void* p) {
    return (unsigned)__cvta_generic_to_shared(p);
}
__device__ __forceinline__ void ldsm4(unsigned& r0, unsigned& r1, unsigned& r2, unsigned& r3, unsigned a) {
    asm volatile("ldmatrix.sync.aligned.m8n8.x4.shared.b16 {%0,%1,%2,%3},[%4];"
                 : "=r"(r0), "=r"(r1), "=r"(r2), "=r"(r3) : "r"(a));
}
__device__ __forceinline__ void ldsm4t(unsigned& r0, unsigned& r1, unsigned& r2, unsigned& r3, unsigned a) {
    asm volatile("ldmatrix.sync.aligned.m8n8.x4.trans.shared.b16 {%0,%1,%2,%3},[%4];"
                 : "=r"(r0), "=r"(r1), "=r"(r2), "=r"(r3) : "r"(a));
}
__device__ __forceinline__ void mma16816(float* c, const unsigned* a, unsigned b0, unsigned b1) {
    asm volatile(
        "mma.sync.aligned.m16n8k16.row.col.f32.f16.f16.f32 "
        "{%0,%1,%2,%3},{%4,%5,%6,%7},{%8,%9},{%0,%1,%2,%3};"
        : "+f"(c[0]), "+f"(c[1]), "+f"(c[2]), "+f"(c[3])
        : "r"(a[0]), "r"(a[1]), "r"(a[2]), "r"(a[3]), "r"(b0), "r"(b1));
}
__device__ __forceinline__ void cp16(unsigned dst, const void* src) {
    asm volatile("cp.async.cg.shared.global [%0],[%1],16;" :: "r"(dst), "l"(src) : "memory");
}
#define CP_COMMIT() asm volatile("cp.async.commit_group;" ::: "memory")
template <int N> __device__ __forceinline__ void cp_wait() {
    asm volatile("cp.async.wait_group %0;" :: "n"(N) : "memory");
}

// ---------------- prep kernels ----------------
__global__ void cvt_w(const float* __restrict__ W) {      // (f,v) f32 -> (v,f) f16
    __shared__ float t[32][33];
    int v0 = blockIdx.x * 32, f0 = blockIdx.y * 32;
    int tx = threadIdx.x, ty = threadIdx.y;  // (32,8)
#pragma unroll
    for (int k = 0; k < 32; k += 8)
        t[ty + k][tx] = W[(size_t)(f0 + ty + k) * V_TOT + v0 + tx];
    __syncthreads();
#pragma unroll
    for (int k = 0; k < 32; k += 8)
        g_W16[(size_t)(v0 + ty + k) * F_DIM + f0 + tx] = __float2half(t[tx][ty + k]);
}

__global__ void cvt_e(const float4* __restrict__ E) {     // (v,d) f32 -> (v,d) f16
    int i = blockIdx.x * blockDim.x + threadIdx.x;
    float4 v = E[i];
    __half2* dst = (__half2*)g_E16;
    dst[2 * (size_t)i]     = __floats2half2_rn(v.x, v.y);
    dst[2 * (size_t)i + 1] = __floats2half2_rn(v.z, v.w);
}

__global__ void cvt_x(const float* __restrict__ x) {      // (B,N,F,T) -> (r,f), r=b*2048+t*64+n
    __shared__ float sm[256][33];
    int bn = blockIdx.x;
    int b = bn >> 6, n = bn & 63;
    const float* src = x + ((size_t)b * 64 + n) * (F_DIM * 32);
    int tid = threadIdx.x;
#pragma unroll 4
    for (int i = tid; i < F_DIM * 32; i += 256) sm[i >> 5][i & 31] = src[i];
    __syncthreads();
#pragma unroll 4
    for (int t = 0; t < 32; ++t) {
        int r = b * 2048 + t * 64 + n;
        g_X16[(size_t)r * F_DIM + tid] = __float2half(sm[tid][t]);
    }
}

__global__ void zero_rsum() {
    g_rsum[blockIdx.x * 1024 + threadIdx.x] = 0.f;
}

// ---------------- pass A: P = exp(X @ W^T + b), rowsum atomics ----------------
// grid (V_TOT/AV = 250, R_TOT/AM = 64), 256 threads, 2 CTAs/SM, k slab-pipelined
__global__ void __launch_bounds__(256, 2)
passA(const float* __restrict__ bias) {
    extern __shared__ __align__(16) __half smem[];
    const unsigned sb = saddr(smem);
    const int tid  = threadIdx.x;
    const int lane = tid & 31;
    const int wid  = tid >> 5;
    const int warp_m = wid >> 1;    // 0..3 (32 rows)
    const int warp_n = wid & 1;     // 0..1 (64 cols)
    const int row_base = blockIdx.y * AM;
    const int v_base   = blockIdx.x * AV;

    const __half* Xsrc = g_X16 + (size_t)row_base * F_DIM;
    const __half* Wsrc = g_W16 + (size_t)v_base * F_DIM;

    auto issue_slab = [&](int s) {
        const int st = s & 1;
        const unsigned xs = sb + (st * A_STAGE_H) * 2;
        const unsigned ws = xs + (AM * AXP) * 2;
        const int k0 = s * ASLAB;
        // X slab: 128 rows x 8 segs (16B) = 1024 segs
#pragma unroll
        for (int i = 0; i < 4; ++i) {
            int idx = tid + i * 256;
            int r = idx >> 3, sg = idx & 7;
            cp16(xs + (r * AXP + sg * 8) * 2, Xsrc + (size_t)r * F_DIM + k0 + sg * 8);
        }
        // W slab: same shape
#pragma unroll
        for (int i = 0; i < 4; ++i) {
            int idx = tid + i * 256;
            int r = idx >> 3, sg = idx & 7;
            cp16(ws + (r * AXP + sg * 8) * 2, Wsrc + (size_t)r * F_DIM + k0 + sg * 8);
        }
        CP_COMMIT();
    };

    float acc[2][8][4];
#pragma unroll
    for (int a = 0; a < 2; a++)
#pragma unroll
        for (int b = 0; b < 8; b++)
#pragma unroll
            for (int c = 0; c < 4; c++) acc[a][b][c] = 0.f;

    issue_slab(0);

    const int m_base = warp_m * 32;
#pragma unroll
    for (int s = 0; s < ANSLAB; ++s) {
        cp_wait<0>();
        __syncthreads();
        if (s + 1 < ANSLAB) issue_slab(s + 1);

        const int st = s & 1;
        const unsigned xs = sb + (st * A_STAGE_H) * 2;
        const unsigned ws = xs + (AM * AXP) * 2;
#pragma unroll
        for (int ks = 0; ks < ASLAB / 16; ++ks) {
            unsigned a0[4], a1[4];
            ldsm4(a0[0], a0[1], a0[2], a0[3],
                  xs + ((m_base + (lane & 15)) * AXP + ks * 16 + ((lane >> 4) << 3)) * 2);
            ldsm4(a1[0], a1[1], a1[2], a1[3],
                  xs + ((m_base + 16 + (lane & 15)) * AXP + ks * 16 + ((lane >> 4) << 3)) * 2);
#pragma unroll
            for (int nb = 0; nb < 4; ++nb) {
                unsigned b0, b1, b2, b3;
                int wrow = warp_n * 64 + nb * 16 + ((lane >> 4) << 3) + (lane & 7);
                int koff = ks * 16 + (((lane >> 3) & 1) << 3);
                ldsm4(b0, b1, b2, b3, ws + (wrow * AXP + koff) * 2);
                mma16816(acc[0][nb * 2],     a0, b0, b1);
                mma16816(acc[0][nb * 2 + 1], a0, b2, b3);
                mma16816(acc[1][nb * 2],     a1, b0, b1);
                mma16816(acc[1][nb * 2 + 1], a1, b2, b3);
            }
        }
    }
    __syncthreads();

    // exp -> fp16 stage + rowsum partials (sums from f16-rounded values)
    float rs[4] = {0.f, 0.f, 0.f, 0.f};
#pragma unroll
    for (int mt = 0; mt < 2; ++mt) {
        int r0 = m_base + mt * 16 + (lane >> 2);
#pragma unroll
        for (int nt = 0; nt < 8; ++nt) {
            int c0 = warp_n * 64 + nt * 8 + (lane & 3) * 2;
            float bv0 = __ldg(bias + v_base + c0);
            float bv1 = __ldg(bias + v_base + c0 + 1);
            float e0 = __expf(acc[mt][nt][0] + bv0);
            float e1 = __expf(acc[mt][nt][1] + bv1);
            __half2 h01 = __floats2half2_rn(e0, e1);
            *(__half2*)(smem + A_P_OFF + r0 * APSP + c0) = h01;
            rs[mt * 2] += __low2float(h01) + __high2float(h01);
            float e2 = __expf(acc[mt][nt][2] + bv0);
            float e3 = __expf(acc[mt][nt][3] + bv1);
            __half2 h23 = __floats2half2_rn(e2, e3);
            *(__half2*)(smem + A_P_OFF + (r0 + 8) * APSP + c0) = h23;
            rs[mt * 2 + 1] += __low2float(h23) + __high2float(h23);
        }
    }
#pragma unroll
    for (int j = 0; j < 4; ++j) {
        rs[j] += __shfl_xor_sync(0xffffffffu, rs[j], 1);
        rs[j] += __shfl_xor_sync(0xffffffffu, rs[j], 2);
    }
    if ((lane & 3) == 0) {
#pragma unroll
        for (int j = 0; j < 4; ++j) {
            int row = m_base + (j >> 1) * 16 + (lane >> 2) + (j & 1) * 8;
            atomicAdd(&g_rsum[row_base + row], rs[j]);
        }
    }
    __syncthreads();

    // coalesced copy stage -> g_P
#pragma unroll
    for (int i = 0; i < 8; ++i) {
        int idx = tid + i * 256;                // 2048 segs of 16B
        int r = idx >> 4, s = idx & 15;
        *(uint4*)(g_P + (size_t)(row_base + r) * V_TOT + v_base + s * 8) =
            *(const uint4*)(smem + A_P_OFF + r * APSP + s * 8);
    }
}

// ---------------- pass B: H = (P @ E) / rowsum ----------------
// grid (D_DIM/BD = 4, R_TOT/BM = 64), 512 threads (16 warps), single sync/chunk
__global__ void __launch_bounds__(512, 1)
passB(float* __restrict__ out) {
    extern __shared__ __align__(16) __half smem[];
    const unsigned sb = saddr(smem);
    const int tid  = threadIdx.x;
    const int lane = tid & 31;
    const int wid  = tid >> 5;
    const int warp_m = wid >> 2;    // 0..3 (32 rows)
    const int warp_n = wid & 3;     // 0..3 (64 cols)
    const int row_base = blockIdx.y * BM;
    const int d_base   = blockIdx.x * BD;

    float hacc[2][8][4];
#pragma unroll
    for (int a = 0; a < 2; a++)
#pragma unroll
        for (int b = 0; b < 8; b++)
#pragma unroll
            for (int c = 0; c < 4; c++) hacc[a][b][c] = 0.f;

    auto issue_chunk = [&](int c) {
        const int st = c & (BSTAGE - 1);
        const unsigned ps = sb + (st * B_STAGE_H + B_P_OFF) * 2;
        const unsigned es = sb + (st * B_STAGE_H + B_E_OFF) * 2;
        const int v0 = c * BKV;
        // P: 128 rows x 8 segs (16B) = 1024
#pragma unroll
        for (int i = 0; i < 2; ++i) {
            int idx = tid + i * 512;
            int r = idx >> 3, s = idx & 7;
            cp16(ps + (r * PP + s * 8) * 2, g_P + (size_t)(row_base + r) * V_TOT + v0 + s * 8);
        }
        // E: 64 rows x 32 segs = 2048
#pragma unroll
        for (int i = 0; i < 4; ++i) {
            int idx = tid + i * 512;
            int r = idx >> 5, s = idx & 31;
            cp16(es + (r * EP + s * 8) * 2, g_E16 + (size_t)(v0 + r) * D_DIM + d_base + s * 8);
        }
        CP_COMMIT();
    };

    issue_chunk(0);
    issue_chunk(1);
    issue_chunk(2);

    const int m_base = warp_m * 32;
    for (int c = 0; c < BNCH; ++c) {
        cp_wait<2>();
        __syncthreads();

        // prefetch chunk c+3 into stage (c-1)&3 (all warps are past iter c-1)
        if (c + 3 < BNCH) issue_chunk(c + 3);
        else CP_COMMIT();   // keep wait_group accounting uniform

        const int st = c & (BSTAGE - 1);
        const unsigned ps = sb + (st * B_STAGE_H + B_P_OFF) * 2;
        const unsigned es = sb + (st * B_STAGE_H + B_E_OFF) * 2;

#pragma unroll
        for (int ks = 0; ks < 4; ++ks) {
            unsigned a0[4], a1[4];
            ldsm4(a0[0], a0[1], a0[2], a0[3],
                  ps + ((m_base + (lane & 15)) * PP + ks * 16 + ((lane >> 4) << 3)) * 2);
            ldsm4(a1[0], a1[1], a1[2], a1[3],
                  ps + ((m_base + 16 + (lane & 15)) * PP + ks * 16 + ((lane >> 4) << 3)) * 2);
#pragma unroll
            for (int np = 0; np < 4; ++np) {
                unsigned b0, b1, b2, b3;
                ldsm4t(b0, b1, b2, b3,
                       es + ((ks * 16 + (lane & 15)) * EP + warp_n * 64 + np * 16 + ((lane >> 4) << 3)) * 2);
                mma16816(hacc[0][np * 2],     a0, b0, b1);
                mma16816(hacc[0][np * 2 + 1], a0, b2, b3);
                mma16816(hacc[1][np * 2],     a1, b0, b1);
                mma16816(hacc[1][np * 2 + 1], a1, b2, b3);
            }
        }
    }

    // epilogue: scale by 1/rowsum, store f32
    float inv[2][2];
#pragma unroll
    for (int mt = 0; mt < 2; ++mt) {
#pragma unroll
        for (int h = 0; h < 2; ++h)
            inv[mt][h] = 1.f / __ldg(&g_rsum[row_base + m_base + mt * 16 + (lane >> 2) + h * 8]);
    }
#pragma unroll
    for (int mt = 0; mt < 2; ++mt) {
        int r0 = row_base + m_base + mt * 16 + (lane >> 2);
#pragma unroll
        for (int nt = 0; nt < 8; ++nt) {
            int col = d_base + warp_n * 64 + nt * 8 + (lane & 3) * 2;
            float2 v0 = make_float2(hacc[mt][nt][0] * inv[mt][0], hacc[mt][nt][1] * inv[mt][0]);
            *(float2*)&out[(size_t)r0 * D_DIM + col] = v0;
            float2 v1 = make_float2(hacc[mt][nt][2] * inv[mt][1], hacc[mt][nt][3] * inv[mt][1]);
            *(float2*)&out[(size_t)(r0 + 8) * D_DIM + col] = v1;
        }
    }
}

// ---------------- launch ----------------
extern "C" void kernel_launch(void* const* d_in, const int* in_sizes, int n_in,
                              void* d_out, int out_size) {
    const float* x   = (const float*)d_in[0];  // (4,64,256,32)
    const float* emb = (const float*)d_in[1];  // (32000,1024)
    const float* W   = (const float*)d_in[2];  // (256,32000)
    const float* b   = (const float*)d_in[3];  // (32000,)
    float* out = (float*)d_out;                // (4,2048,1024)

    cvt_w<<<dim3(V_TOT / 32, F_DIM / 32), dim3(32, 8)>>>(W);
    cvt_e<<<(V_TOT * (D_DIM / 4)) / 256, 256>>>((const float4*)emb);
    cvt_x<<<256, 256>>>(x);
    zero_rsum<<<R_TOT / 1024, 1024>>>();

    cudaFuncSetAttribute(passA, cudaFuncAttributeMaxDynamicSharedMemorySize, A_SMEM_BYTES);
    passA<<<dim3(V_TOT / AV, R_TOT / AM), 256, A_SMEM_BYTES>>>(b);

    cudaFuncSetAttribute(passB, cudaFuncAttributeMaxDynamicSharedMemorySize, B_SMEM_BYTES);
    passB<<<dim3(D_DIM / BD, R_TOT / BM), 512, B_SMEM_BYTES>>>(out);
}

// round 8
// speedup vs baseline: 1.9879x; 1.0602x over previous
#include <cuda_runtime.h>
#include <cuda_fp16.h>
#include <cstdint>

#define V_TOT 32000
#define F_DIM 256
#define D_DIM 1024
#define R_TOT 8192

// pass A tiling (S = X @ W^T, then exp -> P), k streamed in 4 slabs of 64
#define AM 128
#define AV 128
#define ASLAB 64
#define ANSLAB (F_DIM / ASLAB)   // 4
// pass B tiling (H = P @ E): 64x256 tiles, KV=32, 2 CTAs/SM
#define BM 64
#define BD 256
#define BKV 32
#define BSTAGE 4
#define BNCH (V_TOT / BKV)   // 1000

// ---- passA smem (halves) ----
#define AXP 72
#define A_STAGE_H (2 * AM * AXP)                  // 18432 halves per stage
#define A_P_OFF   (2 * A_STAGE_H)                 // 36864
#define APSP 136
#define A_SMEM_BYTES ((A_P_OFF + AM * APSP) * 2)  // 108,544 B -> 2 CTAs/SM

// ---- passB smem (halves) ----
#define PP 40                                     // 32 k + 8 pad
#define EP 264                                    // 256 d + 8 pad
#define B_STAGE_H (BM * PP + BKV * EP)            // 64*40 + 32*264 = 11008 halves
#define B_P_OFF 0
#define B_E_OFF (BM * PP)
#define B_SMEM_BYTES (BSTAGE * B_STAGE_H * 2)     // 88,064 B -> 2 CTAs/SM

// ---------------- static device scratch ----------------
__device__ __half g_W16[(size_t)V_TOT * F_DIM];   // (v, f) fp16
__device__ __half g_E16[(size_t)V_TOT * D_DIM];   // (v, d) fp16
__device__ __half g_X16[(size_t)R_TOT * F_DIM];   // (r, f) fp16 (permuted)
__device__ __half g_P[(size_t)R_TOT * V_TOT];     // (r, v) fp16 unnormalized probs
__device__ float  g_rsum[R_TOT];                  // per-row sum of exp

// ---------------- PTX helpers ----------------
__device__ __forceinline__ unsigned saddr(const void* p) {
    return (unsigned)__cvta_generic_to_shared(p);
}
__device__ __forceinline__ void ldsm4(unsigned& r0, unsigned& r1, unsigned& r2, unsigned& r3, unsigned a) {
    asm volatile("ldmatrix.sync.aligned.m8n8.x4.shared.b16 {%0,%1,%2,%3},[%4];"
                 : "=r"(r0), "=r"(r1), "=r"(r2), "=r"(r3) : "r"(a));
}
__device__ __forceinline__ void ldsm4t(unsigned& r0, unsigned& r1, unsigned& r2, unsigned& r3, unsigned a) {
    asm volatile("ldmatrix.sync.aligned.m8n8.x4.trans.shared.b16 {%0,%1,%2,%3},[%4];"
                 : "=r"(r0), "=r"(r1), "=r"(r2), "=r"(r3) : "r"(a));
}
__device__ __forceinline__ void mma16816(float* c, const unsigned* a, unsigned b0, unsigned b1) {
    asm volatile(
        "mma.sync.aligned.m16n8k16.row.col.f32.f16.f16.f32 "
        "{%0,%1,%2,%3},{%4,%5,%6,%7},{%8,%9},{%0,%1,%2,%3};"
        : "+f"(c[0]), "+f"(c[1]), "+f"(c[2]), "+f"(c[3])
        : "r"(a[0]), "r"(a[1]), "r"(a[2]), "r"(a[3]), "r"(b0), "r"(b1));
}
__device__ __forceinline__ void cp16(unsigned dst, const void* src) {
    asm volatile("cp.async.cg.shared.global [%0],[%1],16;" :: "r"(dst), "l"(src) : "memory");
}
#define CP_COMMIT() asm volatile("cp.async.commit_group;" ::: "memory")
template <int N> __device__ __forceinline__ void cp_wait() {
    asm volatile("cp.async.wait_group %0;" :: "n"(N) : "memory");
}

// ---------------- prep kernels ----------------
__global__ void cvt_w(const float* __restrict__ W) {      // (f,v) f32 -> (v,f) f16
    __shared__ float t[32][33];
    int v0 = blockIdx.x * 32, f0 = blockIdx.y * 32;
    int tx = threadIdx.x, ty = threadIdx.y;  // (32,8)
#pragma unroll
    for (int k = 0; k < 32; k += 8)
        t[ty + k][tx] = W[(size_t)(f0 + ty + k) * V_TOT + v0 + tx];
    __syncthreads();
#pragma unroll
    for (int k = 0; k < 32; k += 8)
        g_W16[(size_t)(v0 + ty + k) * F_DIM + f0 + tx] = __float2half(t[tx][ty + k]);
}

__global__ void cvt_e(const float4* __restrict__ E) {     // (v,d) f32 -> (v,d) f16
    int i = blockIdx.x * blockDim.x + threadIdx.x;
    float4 v = E[i];
    __half2* dst = (__half2*)g_E16;
    dst[2 * (size_t)i]     = __floats2half2_rn(v.x, v.y);
    dst[2 * (size_t)i + 1] = __floats2half2_rn(v.z, v.w);
}

__global__ void cvt_x(const float* __restrict__ x) {      // (B,N,F,T) -> (r,f), r=b*2048+t*64+n
    __shared__ float sm[256][33];
    int bn = blockIdx.x;
    int b = bn >> 6, n = bn & 63;
    const float* src = x + ((size_t)b * 64 + n) * (F_DIM * 32);
    int tid = threadIdx.x;
#pragma unroll 4
    for (int i = tid; i < F_DIM * 32; i += 256) sm[i >> 5][i & 31] = src[i];
    __syncthreads();
#pragma unroll 4
    for (int t = 0; t < 32; ++t) {
        int r = b * 2048 + t * 64 + n;
        g_X16[(size_t)r * F_DIM + tid] = __float2half(sm[tid][t]);
    }
}

__global__ void zero_rsum() {
    g_rsum[blockIdx.x * 1024 + threadIdx.x] = 0.f;
}

// ---------------- pass A: P = exp(X @ W^T + b), rowsum atomics ----------------
// grid (V_TOT/AV = 250, R_TOT/AM = 64), 256 threads, 2 CTAs/SM, k slab-pipelined
__global__ void __launch_bounds__(256, 2)
passA(const float* __restrict__ bias) {
    extern __shared__ __align__(16) __half smem[];
    const unsigned sb = saddr(smem);
    const int tid  = threadIdx.x;
    const int lane = tid & 31;
    const int wid  = tid >> 5;
    const int warp_m = wid >> 1;    // 0..3 (32 rows)
    const int warp_n = wid & 1;     // 0..1 (64 cols)
    const int row_base = blockIdx.y * AM;
    const int v_base   = blockIdx.x * AV;

    const __half* Xsrc = g_X16 + (size_t)row_base * F_DIM;
    const __half* Wsrc = g_W16 + (size_t)v_base * F_DIM;

    auto issue_slab = [&](int s) {
        const int st = s & 1;
        const unsigned xs = sb + (st * A_STAGE_H) * 2;
        const unsigned ws = xs + (AM * AXP) * 2;
        const int k0 = s * ASLAB;
#pragma unroll
        for (int i = 0; i < 4; ++i) {
            int idx = tid + i * 256;
            int r = idx >> 3, sg = idx & 7;
            cp16(xs + (r * AXP + sg * 8) * 2, Xsrc + (size_t)r * F_DIM + k0 + sg * 8);
        }
#pragma unroll
        for (int i = 0; i < 4; ++i) {
            int idx = tid + i * 256;
            int r = idx >> 3, sg = idx & 7;
            cp16(ws + (r * AXP + sg * 8) * 2, Wsrc + (size_t)r * F_DIM + k0 + sg * 8);
        }
        CP_COMMIT();
    };

    float acc[2][8][4];
#pragma unroll
    for (int a = 0; a < 2; a++)
#pragma unroll
        for (int b = 0; b < 8; b++)
#pragma unroll
            for (int c = 0; c < 4; c++) acc[a][b][c] = 0.f;

    issue_slab(0);

    const int m_base = warp_m * 32;
#pragma unroll
    for (int s = 0; s < ANSLAB; ++s) {
        cp_wait<0>();
        __syncthreads();
        if (s + 1 < ANSLAB) issue_slab(s + 1);

        const int st = s & 1;
        const unsigned xs = sb + (st * A_STAGE_H) * 2;
        const unsigned ws = xs + (AM * AXP) * 2;
#pragma unroll
        for (int ks = 0; ks < ASLAB / 16; ++ks) {
            unsigned a0[4], a1[4];
            ldsm4(a0[0], a0[1], a0[2], a0[3],
                  xs + ((m_base + (lane & 15)) * AXP + ks * 16 + ((lane >> 4) << 3)) * 2);
            ldsm4(a1[0], a1[1], a1[2], a1[3],
                  xs + ((m_base + 16 + (lane & 15)) * AXP + ks * 16 + ((lane >> 4) << 3)) * 2);
#pragma unroll
            for (int nb = 0; nb < 4; ++nb) {
                unsigned b0, b1, b2, b3;
                int wrow = warp_n * 64 + nb * 16 + ((lane >> 4) << 3) + (lane & 7);
                int koff = ks * 16 + (((lane >> 3) & 1) << 3);
                ldsm4(b0, b1, b2, b3, ws + (wrow * AXP + koff) * 2);
                mma16816(acc[0][nb * 2],     a0, b0, b1);
                mma16816(acc[0][nb * 2 + 1], a0, b2, b3);
                mma16816(acc[1][nb * 2],     a1, b0, b1);
                mma16816(acc[1][nb * 2 + 1], a1, b2, b3);
            }
        }
    }
    __syncthreads();

    // exp -> fp16 stage + rowsum partials (sums from f16-rounded values)
    float rs[4] = {0.f, 0.f, 0.f, 0.f};
#pragma unroll
    for (int mt = 0; mt < 2; ++mt) {
        int r0 = m_base + mt * 16 + (lane >> 2);
#pragma unroll
        for (int nt = 0; nt < 8; ++nt) {
            int c0 = warp_n * 64 + nt * 8 + (lane & 3) * 2;
            float bv0 = __ldg(bias + v_base + c0);
            float bv1 = __ldg(bias + v_base + c0 + 1);
            float e0 = __expf(acc[mt][nt][0] + bv0);
            float e1 = __expf(acc[mt][nt][1] + bv1);
            __half2 h01 = __floats2half2_rn(e0, e1);
            *(__half2*)(smem + A_P_OFF + r0 * APSP + c0) = h01;
            rs[mt * 2] += __low2float(h01) + __high2float(h01);
            float e2 = __expf(acc[mt][nt][2] + bv0);
            float e3 = __expf(acc[mt][nt][3] + bv1);
            __half2 h23 = __floats2half2_rn(e2, e3);
            *(__half2*)(smem + A_P_OFF + (r0 + 8) * APSP + c0) = h23;
            rs[mt * 2 + 1] += __low2float(h23) + __high2float(h23);
        }
    }
#pragma unroll
    for (int j = 0; j < 4; ++j) {
        rs[j] += __shfl_xor_sync(0xffffffffu, rs[j], 1);
        rs[j] += __shfl_xor_sync(0xffffffffu, rs[j], 2);
    }
    if ((lane & 3) == 0) {
#pragma unroll
        for (int j = 0; j < 4; ++j) {
            int row = m_base + (j >> 1) * 16 + (lane >> 2) + (j & 1) * 8;
            atomicAdd(&g_rsum[row_base + row], rs[j]);
        }
    }
    __syncthreads();

    // coalesced copy stage -> g_P
#pragma unroll
    for (int i = 0; i < 8; ++i) {
        int idx = tid + i * 256;                // 2048 segs of 16B
        int r = idx >> 4, s = idx & 15;
        *(uint4*)(g_P + (size_t)(row_base + r) * V_TOT + v_base + s * 8) =
            *(const uint4*)(smem + A_P_OFF + r * APSP + s * 8);
    }
}

// ---------------- pass B: H = (P @ E) / rowsum ----------------
// grid (D_DIM/BD = 4, R_TOT/BM = 128), 256 threads (8 warps), 2 CTAs/SM
__global__ void __launch_bounds__(256, 2)
passB(float* __restrict__ out) {
    extern __shared__ __align__(16) __half smem[];
    const unsigned sb = saddr(smem);
    const int tid  = threadIdx.x;
    const int lane = tid & 31;
    const int wid  = tid >> 5;
    const int warp_m = wid >> 2;    // 0..1 (32 rows)
    const int warp_n = wid & 3;     // 0..3 (64 cols)
    const int row_base = blockIdx.y * BM;
    const int d_base   = blockIdx.x * BD;

    float hacc[2][8][4];
#pragma unroll
    for (int a = 0; a < 2; a++)
#pragma unroll
        for (int b = 0; b < 8; b++)
#pragma unroll
            for (int c = 0; c < 4; c++) hacc[a][b][c] = 0.f;

    auto issue_chunk = [&](int c) {
        const int st = c & (BSTAGE - 1);
        const unsigned ps = sb + (st * B_STAGE_H + B_P_OFF) * 2;
        const unsigned es = sb + (st * B_STAGE_H + B_E_OFF) * 2;
        const int v0 = c * BKV;
        // P: 64 rows x 4 segs (16B) = 256 segs
        {
            int r = tid >> 2, s = tid & 3;
            cp16(ps + (r * PP + s * 8) * 2, g_P + (size_t)(row_base + r) * V_TOT + v0 + s * 8);
        }
        // E: 32 rows x 32 segs = 1024 segs
#pragma unroll
        for (int i = 0; i < 4; ++i) {
            int idx = tid + i * 256;
            int r = idx >> 5, s = idx & 31;
            cp16(es + (r * EP + s * 8) * 2, g_E16 + (size_t)(v0 + r) * D_DIM + d_base + s * 8);
        }
        CP_COMMIT();
    };

    issue_chunk(0);
    issue_chunk(1);
    issue_chunk(2);

    const int m_base = warp_m * 32;
    for (int c = 0; c < BNCH; ++c) {
        cp_wait<2>();
        __syncthreads();

        // prefetch chunk c+3 into stage (c-1)&3 (all warps are past iter c-1)
        if (c + 3 < BNCH) issue_chunk(c + 3);
        else CP_COMMIT();   // keep wait_group accounting uniform

        const int st = c & (BSTAGE - 1);
        const unsigned ps = sb + (st * B_STAGE_H + B_P_OFF) * 2;
        const unsigned es = sb + (st * B_STAGE_H + B_E_OFF) * 2;

#pragma unroll
        for (int ks = 0; ks < BKV / 16; ++ks) {
            unsigned a0[4], a1[4];
            ldsm4(a0[0], a0[1], a0[2], a0[3],
                  ps + ((m_base + (lane & 15)) * PP + ks * 16 + ((lane >> 4) << 3)) * 2);
            ldsm4(a1[0], a1[1], a1[2], a1[3],
                  ps + ((m_base + 16 + (lane & 15)) * PP + ks * 16 + ((lane >> 4) << 3)) * 2);
#pragma unroll
            for (int np = 0; np < 4; ++np) {
                unsigned b0, b1, b2, b3;
                ldsm4t(b0, b1, b2, b3,
                       es + ((ks * 16 + (lane & 15)) * EP + warp_n * 64 + np * 16 + ((lane >> 4) << 3)) * 2);
                mma16816(hacc[0][np * 2],     a0, b0, b1);
                mma16816(hacc[0][np * 2 + 1], a0, b2, b3);
                mma16816(hacc[1][np * 2],     a1, b0, b1);
                mma16816(hacc[1][np * 2 + 1], a1, b2, b3);
            }
        }
    }

    // epilogue: scale by 1/rowsum, store f32
    float inv[2][2];
#pragma unroll
    for (int mt = 0; mt < 2; ++mt) {
#pragma unroll
        for (int h = 0; h < 2; ++h)
            inv[mt][h] = 1.f / __ldg(&g_rsum[row_base + m_base + mt * 16 + (lane >> 2) + h * 8]);
    }
#pragma unroll
    for (int mt = 0; mt < 2; ++mt) {
        int r0 = row_base + m_base + mt * 16 + (lane >> 2);
#pragma unroll
        for (int nt = 0; nt < 8; ++nt) {
            int col = d_base + warp_n * 64 + nt * 8 + (lane & 3) * 2;
            float2 v0 = make_float2(hacc[mt][nt][0] * inv[mt][0], hacc[mt][nt][1] * inv[mt][0]);
            *(float2*)&out[(size_t)r0 * D_DIM + col] = v0;
            float2 v1 = make_float2(hacc[mt][nt][2] * inv[mt][1], hacc[mt][nt][3] * inv[mt][1]);
            *(float2*)&out[(size_t)(r0 + 8) * D_DIM + col] = v1;
        }
    }
}

// ---------------- launch ----------------
extern "C" void kernel_launch(void* const* d_in, const int* in_sizes, int n_in,
                              void* d_out, int out_size) {
    const float* x   = (const float*)d_in[0];  // (4,64,256,32)
    const float* emb = (const float*)d_in[1];  // (32000,1024)
    const float* W   = (const float*)d_in[2];  // (256,32000)
    const float* b   = (const float*)d_in[3];  // (32000,)
    float* out = (float*)d_out;                // (4,2048,1024)

    cvt_w<<<dim3(V_TOT / 32, F_DIM / 32), dim3(32, 8)>>>(W);
    cvt_e<<<(V_TOT * (D_DIM / 4)) / 256, 256>>>((const float4*)emb);
    cvt_x<<<256, 256>>>(x);
    zero_rsum<<<R_TOT / 1024, 1024>>>();

    cudaFuncSetAttribute(passA, cudaFuncAttributeMaxDynamicSharedMemorySize, A_SMEM_BYTES);
    passA<<<dim3(V_TOT / AV, R_TOT / AM), 256, A_SMEM_BYTES>>>(b);

    cudaFuncSetAttribute(passB, cudaFuncAttributeMaxDynamicSharedMemorySize, B_SMEM_BYTES);
    passB<<<dim3(D_DIM / BD, R_TOT / BM), 256, B_SMEM_BYTES>>>(out);
}